// round 15
// baseline (speedup 1.0000x reference)
#include <cuda_runtime.h>
#include <cuda_fp16.h>
#include <cstdint>

// Problem dims (fixed by the dataset)
#define B_   16
#define CIN  256
#define COUT 256
#define H_   64
#define W_   64
#define NK   4    // kernel_number n

// Padded-pixel geometry: 66x66 grid flattened; tap shift = (dh-1)*66+(dw-1)
#define POFF   68          // row margin so shifted reads never go negative
#define PROWS  4616
#define NTILE  128         // pixels (M) per CTA
#define NTILES 35          // ceil(4356/128)

// -------------------- device scratch (static, no allocs) --------------------
__device__ __align__(256) __half g_x16[(size_t)B_ * PROWS * CIN];
__device__ __align__(256) __half g_w16[(size_t)B_ * 9 * COUT * CIN];

// -------------------- PTX helpers (plain sm_90-safe, no 'a' features) ------
__device__ __forceinline__ uint32_t smem_u32(const void* p) {
    uint32_t a;
    asm("{ .reg .u64 t; cvta.to.shared.u64 t, %1; cvt.u32.u64 %0, t; }"
        : "=r"(a) : "l"(p));
    return a;
}

#define CP16(dst, src) \
    asm volatile("cp.async.cg.shared.global [%0], [%1], 16;" \
                 :: "r"(dst), "l"(src) : "memory")
#define CP_COMMIT() asm volatile("cp.async.commit_group;" ::: "memory")
#define CP_WAIT1()  asm volatile("cp.async.wait_group 1;" ::: "memory")
#define CP_WAIT0()  asm volatile("cp.async.wait_group 0;" ::: "memory")

__device__ __forceinline__ void ldm4(uint32_t& r0, uint32_t& r1,
                                     uint32_t& r2, uint32_t& r3, uint32_t a) {
    asm volatile("ldmatrix.sync.aligned.m8n8.x4.shared.b16 {%0,%1,%2,%3}, [%4];"
                 : "=r"(r0), "=r"(r1), "=r"(r2), "=r"(r3) : "r"(a));
}

__device__ __forceinline__ void mma16816(float* c, const uint32_t* a,
                                         const uint32_t* b) {
    asm volatile(
        "mma.sync.aligned.m16n8k16.row.col.f32.f16.f16.f32 "
        "{%0,%1,%2,%3}, {%4,%5,%6,%7}, {%8,%9}, {%0,%1,%2,%3};"
        : "+f"(c[0]), "+f"(c[1]), "+f"(c[2]), "+f"(c[3])
        : "r"(a[0]), "r"(a[1]), "r"(a[2]), "r"(a[3]), "r"(b[0]), "r"(b[1]));
}

// ---------------------------------------------------------------------------
// rot matrix builder (device function)
// ---------------------------------------------------------------------------
__device__ void compute_rot(float t, float s, float lam, float* dst) {
    float x = cosf(t) * s;
    float y = sinf(t) * s;

    float m[81];
#pragma unroll
    for (int k = 0; k < 81; k++) m[k] = 0.f;
    m[4 * 9 + 4] = 1.f;

#define SET(r, c, v) m[(r) * 9 + (c)] = (v)
    bool pos = (t >= 0.f);
    bool big = (s >= 1.f);
    bool one = (fabsf(t) <= 0.78539816339744830962f);

    if (pos) {
        float a = x - y, b = x * y, c = x + y;
        float d = a * c, e = a + c;
        if (one && big) {
            SET(0,0,a);     SET(0,1,1.f-a);
            SET(1,1,1.f-y); SET(1,2,y);
            SET(2,2,a);     SET(2,5,1.f-a);
            SET(3,0,y);     SET(3,3,1.f-y);
            SET(5,5,1.f-y); SET(5,8,y);
            SET(6,3,1.f-a); SET(6,6,a);
            SET(7,6,y);     SET(7,7,1.f-y);
            SET(8,7,1.f-a); SET(8,8,a);
        } else if (one) {
            SET(0,0,d);       SET(0,1,a-d);     SET(0,3,c-d);     SET(0,4,1.f-e+d);
            SET(1,1,x-b);     SET(1,2,b);       SET(1,4,1.f-c+b); SET(1,5,y-b);
            SET(2,1,c-d);     SET(2,2,d);       SET(2,4,1.f-e+d); SET(2,5,a-d);
            SET(3,0,b);       SET(3,1,y-b);     SET(3,3,x-b);     SET(3,4,1.f-c+b);
            SET(5,4,1.f-c+b); SET(5,5,x-b);     SET(5,7,y-b);     SET(5,8,b);
            SET(6,3,a-d);     SET(6,4,1.f-e+d); SET(6,6,d);       SET(6,7,c-d);
            SET(7,3,y-b);     SET(7,4,1.f-c+b); SET(7,6,b);       SET(7,7,x-b);
            SET(8,4,1.f-e+d); SET(8,5,c-d);     SET(8,7,a-d);     SET(8,8,d);
        } else {
            SET(0,0,a);       SET(0,1,1.f-a);
            SET(1,1,x-b);     SET(1,2,b);       SET(1,4,1.f-c+b); SET(1,5,y-b);
            SET(2,2,a);       SET(2,5,1.f-a);
            SET(3,0,b);       SET(3,1,y-b);     SET(3,3,x-b);     SET(3,4,1.f-c+b);
            SET(5,4,1.f-c+b); SET(5,5,x-b);     SET(5,7,y-b);     SET(5,8,b);
            SET(6,3,1.f-a);   SET(6,6,a);
            SET(7,3,y-b);     SET(7,4,1.f-c+b); SET(7,6,b);       SET(7,7,x-b);
            SET(8,7,1.f-a);   SET(8,8,a);
        }
    } else {
        float yp = -y;
        float ap = x - yp, bp = x * yp, cp = x + yp;
        float dp = ap * cp, ep = ap + cp;
        if (one && big) {
            SET(0,0,cp);     SET(0,3,1.f-cp);
            SET(1,0,yp);     SET(1,1,1.f-yp);
            SET(2,1,1.f-cp); SET(2,2,cp);
            SET(3,3,1.f-yp); SET(3,6,yp);
            SET(5,2,yp);     SET(5,5,1.f-yp);
            SET(6,6,cp);     SET(6,7,1.f-cp);
            SET(7,7,1.f-yp); SET(7,8,yp);
            SET(8,5,1.f-cp); SET(8,8,cp);
        } else if (one) {
            SET(0,0,dp);        SET(0,1,cp-dp);     SET(0,3,ap-dp);     SET(0,4,1.f-ep+dp);
            SET(1,0,bp);        SET(1,1,x-bp);      SET(1,3,yp-bp);     SET(1,4,1.f-cp+bp);
            SET(2,1,ap-dp);     SET(2,2,dp);        SET(2,4,1.f-ep+dp); SET(2,5,cp-dp);
            SET(3,1,yp-bp);     SET(3,2,bp);        SET(3,4,1.f-cp+bp); SET(3,5,x-bp);
            SET(5,3,x-bp);      SET(5,4,1.f-cp+bp); SET(5,6,bp);        SET(5,7,yp-bp);
            SET(6,3,cp-dp);     SET(6,4,1.f-ep+dp); SET(6,6,dp);        SET(6,7,ap-dp);
            SET(7,4,1.f-cp+bp); SET(7,5,yp-bp);     SET(7,7,x-bp);      SET(7,8,bp);
            SET(8,4,1.f-ep+dp); SET(8,5,ap-dp);     SET(8,7,cp-dp);     SET(8,8,dp);
        } else {
            SET(0,0,cp);        SET(0,3,1.f-cp);
            SET(1,0,bp);        SET(1,1,x-bp);      SET(1,3,yp-bp);     SET(1,4,1.f-cp+bp);
            SET(2,1,1.f-cp);    SET(2,2,cp);
            SET(3,3,x-bp);      SET(3,4,1.f-cp+bp); SET(3,6,bp);        SET(3,7,yp-bp);
            SET(5,1,yp-bp);     SET(5,2,bp);        SET(5,4,1.f-cp+bp); SET(5,5,x-bp);
            SET(6,6,cp);        SET(6,7,1.f-cp);
            SET(7,4,1.f-cp+bp); SET(7,5,yp-bp);     SET(7,7,x-bp);      SET(7,8,bp);
            SET(8,5,1.f-cp);    SET(8,8,cp);
        }
    }
#undef SET

#pragma unroll
    for (int k = 0; k < 81; k++) dst[k] = lam * m[k];
}

// ---------------------------------------------------------------------------
// Kernel B: weight transform -> fp16. One block per co; weight slice and all
// 64 rot matrices cached in smem; loop over batches (weight read ONCE).
// ---------------------------------------------------------------------------
__global__ void __launch_bounds__(256)
wtrans_kernel(const float* __restrict__ weight,
              const float* __restrict__ thetas,
              const float* __restrict__ scales,
              const float* __restrict__ lambdas) {
    int o = blockIdx.x;     // co
    int c = threadIdx.x;    // ci

    __shared__ float Rs[B_ * NK * 81];        // 20736 B
    __shared__ float Ws[NK][CIN][9];          // 36864 B

    if (threadIdx.x < B_ * NK) {
        int id = threadIdx.x;                 // b*NK + n
        compute_rot(thetas[id], scales[id], lambdas[id], Rs + id * 81);
    }
#pragma unroll
    for (int n = 0; n < NK; n++) {
        const float* wp = weight + (((size_t)n * COUT + o) * CIN) * 9;
        for (int k = threadIdx.x; k < CIN * 9; k += 256)
            Ws[n][k / 9][k % 9] = wp[k];
    }
    __syncthreads();

    float w9[NK][9];
#pragma unroll
    for (int n = 0; n < NK; n++)
#pragma unroll
        for (int j = 0; j < 9; j++) w9[n][j] = Ws[n][c][j];

    for (int b = 0; b < B_; b++) {
        float acc[9];
#pragma unroll
        for (int i = 0; i < 9; i++) acc[i] = 0.f;
#pragma unroll
        for (int n = 0; n < NK; n++) {
            const float* R = Rs + (b * NK + n) * 81;
#pragma unroll
            for (int i = 0; i < 9; i++)
#pragma unroll
                for (int j = 0; j < 9; j++)
                    acc[i] += R[i * 9 + j] * w9[n][j];
        }
#pragma unroll
        for (int i = 0; i < 9; i++) {
            size_t idx = (((size_t)b * 9 + i) * COUT + o) * CIN + c;
            g_w16[idx] = __float2half(acc[i]);
        }
    }
}

// ---------------------------------------------------------------------------
// Kernel X: transpose + pad + fp16 convert of x, PLUS margin zeroing.
// grid (H_, B_): block (h,b). Margin rows of batch b are zeroed by the h-blocks
// (rows disjoint from interior rows written below; no sync needed).
// ---------------------------------------------------------------------------
__global__ void xprep_kernel(const float* __restrict__ x) {
    __shared__ float t[64][65];
    int h = blockIdx.x, b = blockIdx.y;

    // ---- margin zeroing: batch b has 520 non-interior rows; split over 64 h-blocks
    {
        // enumerate non-interior rows: pr in [0, PROWS); interior iff
        // pr-POFF in [0,4356) and maps to hp in [1,64], wp in [1,64]
        // chunk: each block handles rows  h*72 .. h*72+71  of the margin index space?
        // simpler: stride over all PROWS rows with 64 blocks, test + zero.
        for (int pr = h; pr < PROWS; pr += H_) {
            int p = pr - POFF;
            bool interior = false;
            if (p >= 0 && p < 66 * 66) {
                int hp = p / 66, wp = p - hp * 66;
                interior = (hp >= 1 && hp <= 64 && wp >= 1 && wp <= 64);
            }
            if (!interior) {
                uint4* dst = (uint4*)(g_x16 + ((size_t)b * PROWS + pr) * CIN);
                for (int i = threadIdx.x; i < 32; i += 256)
                    dst[i] = make_uint4(0, 0, 0, 0);
            }
        }
    }

    for (int ci0 = 0; ci0 < CIN; ci0 += 64) {
        __syncthreads();
        for (int i = threadIdx.x; i < 64 * 64; i += 256) {
            int cl = i >> 6, w = i & 63;
            t[cl][w] = x[(((size_t)b * CIN + ci0 + cl) * H_ + h) * W_ + w];
        }
        __syncthreads();
        for (int i = threadIdx.x; i < 64 * 64; i += 256) {
            int w = i >> 6, cl = i & 63;
            size_t row = (size_t)b * PROWS + ((h + 1) * 66 + (w + 1) + POFF);
            g_x16[row * CIN + ci0 + cl] = __float2half(t[cl][w]);
        }
    }
}

// ---------------------------------------------------------------------------
// Kernel C: implicit-GEMM conv via mma.sync (fp16 in, fp32 accum).
// CTA: 128 pixels x 128 cout, 8 warps (2M x 4N), warp tile 64x32.
// 2 CTAs/SM; 36 stages, cp.async 3-stage ring, ONE barrier/stage.
// PHASE OFFSET: cob=1 CTAs process stages rotated by 18 so co-resident CTAs
// don't run in lockstep (barriers interleave instead of colliding).
// ---------------------------------------------------------------------------
#define LDT     144u                 // smem row stride bytes (9 x 16B)
#define A_TILE  (128u * LDT)         // 18432 B
#define B_TILE  (128u * LDT)         // 18432 B
#define OFF_A   0u
#define OFF_B   A_TILE
#define STG_B   (A_TILE + B_TILE)    // 36864 B per stage
#define SMEM_BYTES (3u * STG_B)      // 110592 B

__device__ __forceinline__ void stage_tiles(uint32_t sdst,
                                            const char* X, const char* W,
                                            int c0, int ss, int tid) {
    const int tap = ss >> 2, kc = ss & 3;
    const int dlt = (tap / 3 - 1) * 66 + (tap % 3) - 1;
    const char* sA = X + ((size_t)(c0 + dlt + POFF) * CIN + kc * 64) * 2;
    const char* sB = W + ((size_t)tap * COUT * CIN + kc * 64) * 2;   // W pre-offset by co0
#pragma unroll
    for (int j = 0; j < 4; j++) {
        int idx = j * 256 + tid;              // 0..1023
        int row = idx >> 3, seg = idx & 7;
        CP16(sdst + OFF_A + row * LDT + seg * 16,
             sA + (size_t)row * (CIN * 2) + seg * 16);
    }
#pragma unroll
    for (int j = 0; j < 4; j++) {
        int idx = j * 256 + tid;              // 0..1023
        int row = idx >> 3, seg = idx & 7;
        CP16(sdst + OFF_B + row * LDT + seg * 16,
             sB + (size_t)row * (CIN * 2) + seg * 16);
    }
}

__global__ void __launch_bounds__(256, 2)
conv_mma_kernel(float* __restrict__ out) {
    extern __shared__ char smem[];
    const uint32_t sb = smem_u32(smem);

    const int tid = threadIdx.x;
    const int wid = tid >> 5, lane = tid & 31;
    const int wm = wid >> 2;         // 0..1 : M half (64 rows)
    const int wn = wid & 3;          // 0..3 : N quarter (32 cols)
    const int tile = blockIdx.x, cob = blockIdx.y, b = blockIdx.z;
    const int c0 = tile * NTILE;
    const int co0 = cob * 128;
    const int phase = cob * 18;      // de-lockstep offset

    const char* X = (const char*)(g_x16 + (size_t)b * PROWS * CIN);
    const char* W = (const char*)(g_w16 + ((size_t)b * 9 * COUT + co0) * CIN);

    float acc[4][4][4];
#pragma unroll
    for (int mt = 0; mt < 4; mt++)
#pragma unroll
        for (int nt = 0; nt < 4; nt++)
#pragma unroll
            for (int k = 0; k < 4; k++) acc[mt][nt][k] = 0.f;

    const uint32_t aRow = (uint32_t)(wm * 64 + (lane & 15)) * LDT + (lane >> 4) * 16;
    const uint32_t bRow = (uint32_t)(wn * 32 + ((lane >> 4) * 8 + (lane & 7))) * LDT
                          + ((lane >> 3) & 1) * 16;

    {
        int s0 = phase;                       // stage 0 (rotated)
        int s1 = phase + 1; if (s1 >= 36) s1 -= 36;
        stage_tiles(sb + 0u * STG_B, X, W, c0, s0, tid);
        CP_COMMIT();
        stage_tiles(sb + 1u * STG_B, X, W, c0, s1, tid);
        CP_COMMIT();
    }

    int bufSel = 0;                   // st % 3 without modulo
    int ssNext = phase + 2; if (ssNext >= 36) ssNext -= 36;
    for (int st = 0; st < 36; st++) {
        if (st < 35) CP_WAIT1(); else CP_WAIT0();
        __syncthreads();              // stage st visible; ring slot st+2 free

        // prefetch st+2 BEFORE compute so cp.async latency hides under mma
        if (st + 2 < 36) {
            int slot = bufSel + 2; if (slot >= 3) slot -= 3;
            stage_tiles(sb + (uint32_t)slot * STG_B, X, W, c0, ssNext, tid);
            CP_COMMIT();
            if (++ssNext >= 36) ssNext -= 36;
        }

        const uint32_t buf = sb + (uint32_t)bufSel * STG_B;
#pragma unroll
        for (int ks = 0; ks < 4; ks++) {
            const uint32_t kb = ks * 32;
            uint32_t a[4][4];
#pragma unroll
            for (int mt = 0; mt < 4; mt++)
                ldm4(a[mt][0], a[mt][1], a[mt][2], a[mt][3],
                     buf + OFF_A + aRow + mt * (16 * LDT) + kb);
#pragma unroll
            for (int pr = 0; pr < 2; pr++) {     // nt pairs
                uint32_t bb[2][2];
                ldm4(bb[0][0], bb[0][1], bb[1][0], bb[1][1],
                     buf + OFF_B + bRow + pr * (16 * LDT) + kb);
#pragma unroll
                for (int mt = 0; mt < 4; mt++) {
                    mma16816(acc[mt][pr * 2],     a[mt], bb[0]);
                    mma16816(acc[mt][pr * 2 + 1], a[mt], bb[1]);
                }
            }
        }

        if (++bufSel == 3) bufSel = 0;
    }

    // ---- epilogue: fragment -> gmem ----
    const int grp = lane >> 2;
#pragma unroll
    for (int mt = 0; mt < 4; mt++) {
#pragma unroll
        for (int half = 0; half < 2; half++) {
            int p = c0 + wm * 64 + mt * 16 + grp + half * 8;
            int hp = p / 66, wp = p - hp * 66;
            if (hp < 1 || hp > 64 || wp < 1 || wp > 64) continue;
            size_t base = (((size_t)b * COUT + co0 + wn * 32) * H_ + (hp - 1)) * W_
                          + (wp - 1);
#pragma unroll
            for (int nt = 0; nt < 4; nt++) {
                int cofs = nt * 8 + (lane & 3) * 2;
                out[base + (size_t)cofs * (H_ * W_)]       = acc[mt][nt][half * 2];
                out[base + (size_t)(cofs + 1) * (H_ * W_)] = acc[mt][nt][half * 2 + 1];
            }
        }
    }
}

// ---------------------------------------------------------------------------
extern "C" void kernel_launch(void* const* d_in, const int* in_sizes, int n_in,
                              void* d_out, int out_size) {
    const float* x       = (const float*)d_in[0];
    const float* thetas  = (const float*)d_in[1];
    const float* scales  = (const float*)d_in[2];
    const float* lambdas = (const float*)d_in[3];
    const float* weight  = (const float*)d_in[4];
    float* out = (float*)d_out;

    cudaFuncSetAttribute(conv_mma_kernel,
                         cudaFuncAttributeMaxDynamicSharedMemorySize, SMEM_BYTES);

    wtrans_kernel<<<COUT, 256>>>(weight, thetas, scales, lambdas);
    xprep_kernel<<<dim3(H_, B_), 256>>>(x);
    conv_mma_kernel<<<dim3(NTILES, 2, B_), 256, SMEM_BYTES>>>(out);
}

// round 17
// speedup vs baseline: 1.6176x; 1.6176x over previous
#include <cuda_runtime.h>
#include <cuda_fp16.h>
#include <cstdint>

// Problem dims (fixed by the dataset)
#define B_   16
#define CIN  256
#define COUT 256
#define H_   64
#define W_   64
#define NK   4    // kernel_number n

// Padded-pixel geometry: 66x66 grid flattened; tap shift = (dh-1)*66+(dw-1)
#define POFF   68          // row margin so shifted reads never go negative
#define PROWS  4616
#define NTILE  128         // pixels (M) per CTA
#define NTILES 35          // ceil(4356/128)

// -------------------- device scratch (static, no allocs) --------------------
__device__ __align__(256) __half g_x16[(size_t)B_ * PROWS * CIN];
__device__ __align__(256) __half g_w16[(size_t)B_ * 9 * COUT * CIN];

// -------------------- PTX helpers (plain sm_90-safe, no 'a' features) ------
__device__ __forceinline__ uint32_t smem_u32(const void* p) {
    uint32_t a;
    asm("{ .reg .u64 t; cvta.to.shared.u64 t, %1; cvt.u32.u64 %0, t; }"
        : "=r"(a) : "l"(p));
    return a;
}

#define CP16(dst, src) \
    asm volatile("cp.async.cg.shared.global [%0], [%1], 16;" \
                 :: "r"(dst), "l"(src) : "memory")
#define CP_COMMIT() asm volatile("cp.async.commit_group;" ::: "memory")
#define CP_WAIT1()  asm volatile("cp.async.wait_group 1;" ::: "memory")
#define CP_WAIT0()  asm volatile("cp.async.wait_group 0;" ::: "memory")

__device__ __forceinline__ void ldm4(uint32_t& r0, uint32_t& r1,
                                     uint32_t& r2, uint32_t& r3, uint32_t a) {
    asm volatile("ldmatrix.sync.aligned.m8n8.x4.shared.b16 {%0,%1,%2,%3}, [%4];"
                 : "=r"(r0), "=r"(r1), "=r"(r2), "=r"(r3) : "r"(a));
}

__device__ __forceinline__ void mma16816(float* c, const uint32_t* a,
                                         const uint32_t* b) {
    asm volatile(
        "mma.sync.aligned.m16n8k16.row.col.f32.f16.f16.f32 "
        "{%0,%1,%2,%3}, {%4,%5,%6,%7}, {%8,%9}, {%0,%1,%2,%3};"
        : "+f"(c[0]), "+f"(c[1]), "+f"(c[2]), "+f"(c[3])
        : "r"(a[0]), "r"(a[1]), "r"(a[2]), "r"(a[3]), "r"(b[0]), "r"(b[1]));
}

// ---------------------------------------------------------------------------
// rot matrix builder (device function)
// ---------------------------------------------------------------------------
__device__ void compute_rot(float t, float s, float lam, float* dst) {
    float x = cosf(t) * s;
    float y = sinf(t) * s;

    float m[81];
#pragma unroll
    for (int k = 0; k < 81; k++) m[k] = 0.f;
    m[4 * 9 + 4] = 1.f;

#define SET(r, c, v) m[(r) * 9 + (c)] = (v)
    bool pos = (t >= 0.f);
    bool big = (s >= 1.f);
    bool one = (fabsf(t) <= 0.78539816339744830962f);

    if (pos) {
        float a = x - y, b = x * y, c = x + y;
        float d = a * c, e = a + c;
        if (one && big) {
            SET(0,0,a);     SET(0,1,1.f-a);
            SET(1,1,1.f-y); SET(1,2,y);
            SET(2,2,a);     SET(2,5,1.f-a);
            SET(3,0,y);     SET(3,3,1.f-y);
            SET(5,5,1.f-y); SET(5,8,y);
            SET(6,3,1.f-a); SET(6,6,a);
            SET(7,6,y);     SET(7,7,1.f-y);
            SET(8,7,1.f-a); SET(8,8,a);
        } else if (one) {
            SET(0,0,d);       SET(0,1,a-d);     SET(0,3,c-d);     SET(0,4,1.f-e+d);
            SET(1,1,x-b);     SET(1,2,b);       SET(1,4,1.f-c+b); SET(1,5,y-b);
            SET(2,1,c-d);     SET(2,2,d);       SET(2,4,1.f-e+d); SET(2,5,a-d);
            SET(3,0,b);       SET(3,1,y-b);     SET(3,3,x-b);     SET(3,4,1.f-c+b);
            SET(5,4,1.f-c+b); SET(5,5,x-b);     SET(5,7,y-b);     SET(5,8,b);
            SET(6,3,a-d);     SET(6,4,1.f-e+d); SET(6,6,d);       SET(6,7,c-d);
            SET(7,3,y-b);     SET(7,4,1.f-c+b); SET(7,6,b);       SET(7,7,x-b);
            SET(8,4,1.f-e+d); SET(8,5,c-d);     SET(8,7,a-d);     SET(8,8,d);
        } else {
            SET(0,0,a);       SET(0,1,1.f-a);
            SET(1,1,x-b);     SET(1,2,b);       SET(1,4,1.f-c+b); SET(1,5,y-b);
            SET(2,2,a);       SET(2,5,1.f-a);
            SET(3,0,b);       SET(3,1,y-b);     SET(3,3,x-b);     SET(3,4,1.f-c+b);
            SET(5,4,1.f-c+b); SET(5,5,x-b);     SET(5,7,y-b);     SET(5,8,b);
            SET(6,3,1.f-a);   SET(6,6,a);
            SET(7,3,y-b);     SET(7,4,1.f-c+b); SET(7,6,b);       SET(7,7,x-b);
            SET(8,7,1.f-a);   SET(8,8,a);
        }
    } else {
        float yp = -y;
        float ap = x - yp, bp = x * yp, cp = x + yp;
        float dp = ap * cp, ep = ap + cp;
        if (one && big) {
            SET(0,0,cp);     SET(0,3,1.f-cp);
            SET(1,0,yp);     SET(1,1,1.f-yp);
            SET(2,1,1.f-cp); SET(2,2,cp);
            SET(3,3,1.f-yp); SET(3,6,yp);
            SET(5,2,yp);     SET(5,5,1.f-yp);
            SET(6,6,cp);     SET(6,7,1.f-cp);
            SET(7,7,1.f-yp); SET(7,8,yp);
            SET(8,5,1.f-cp); SET(8,8,cp);
        } else if (one) {
            SET(0,0,dp);        SET(0,1,cp-dp);     SET(0,3,ap-dp);     SET(0,4,1.f-ep+dp);
            SET(1,0,bp);        SET(1,1,x-bp);      SET(1,3,yp-bp);     SET(1,4,1.f-cp+bp);
            SET(2,1,ap-dp);     SET(2,2,dp);        SET(2,4,1.f-ep+dp); SET(2,5,cp-dp);
            SET(3,1,yp-bp);     SET(3,2,bp);        SET(3,4,1.f-cp+bp); SET(3,5,x-bp);
            SET(5,3,x-bp);      SET(5,4,1.f-cp+bp); SET(5,6,bp);        SET(5,7,yp-bp);
            SET(6,3,cp-dp);     SET(6,4,1.f-ep+dp); SET(6,6,dp);        SET(6,7,ap-dp);
            SET(7,4,1.f-cp+bp); SET(7,5,yp-bp);     SET(7,7,x-bp);      SET(7,8,bp);
            SET(8,4,1.f-ep+dp); SET(8,5,ap-dp);     SET(8,7,cp-dp);     SET(8,8,dp);
        } else {
            SET(0,0,cp);        SET(0,3,1.f-cp);
            SET(1,0,bp);        SET(1,1,x-bp);      SET(1,3,yp-bp);     SET(1,4,1.f-cp+bp);
            SET(2,1,1.f-cp);    SET(2,2,cp);
            SET(3,3,x-bp);      SET(3,4,1.f-cp+bp); SET(3,6,bp);        SET(3,7,yp-bp);
            SET(5,1,yp-bp);     SET(5,2,bp);        SET(5,4,1.f-cp+bp); SET(5,5,x-bp);
            SET(6,6,cp);        SET(6,7,1.f-cp);
            SET(7,4,1.f-cp+bp); SET(7,5,yp-bp);     SET(7,7,x-bp);      SET(7,8,bp);
            SET(8,5,1.f-cp);    SET(8,8,cp);
        }
    }
#undef SET

#pragma unroll
    for (int k = 0; k < 81; k++) dst[k] = lam * m[k];
}

// ---------------------------------------------------------------------------
// Fused prep kernel — ONE launch for wtrans + xprep + margin zeroing.
// grid (256, B_, 2):
//   z==1           : wtrans, o=blockIdx.x, b=blockIdx.y  (R13 wtrans body)
//   z==0, x <  64  : xprep,  h=blockIdx.x, b=blockIdx.y  (R13 xprep body)
//   z==0, x >= 64  : margin zeroing, 192 blocks x 8 warps stride over rows
// ---------------------------------------------------------------------------
__global__ void __launch_bounds__(256)
prep_kernel(const float* __restrict__ x,
            const float* __restrict__ weight,
            const float* __restrict__ thetas,
            const float* __restrict__ scales,
            const float* __restrict__ lambdas) {
    __shared__ union {
        float t[64][65];          // xprep transpose buffer
        float Rs[NK * 81];        // wtrans rot cache
    } sm;

    const int b = blockIdx.y;

    if (blockIdx.z == 1) {
        // ---------------- wtrans (exact R13 logic) ----------------
        int o = blockIdx.x;     // co
        int c = threadIdx.x;    // ci

        if (threadIdx.x < NK) {
            int id = b * NK + threadIdx.x;
            compute_rot(thetas[id], scales[id], lambdas[id],
                        sm.Rs + threadIdx.x * 81);
        }
        __syncthreads();

        float acc[9];
#pragma unroll
        for (int i = 0; i < 9; i++) acc[i] = 0.f;

#pragma unroll
        for (int n = 0; n < NK; n++) {
            float w9[9];
            const float* wp = weight + (((size_t)n * COUT + o) * CIN + c) * 9;
#pragma unroll
            for (int j = 0; j < 9; j++) w9[j] = wp[j];
#pragma unroll
            for (int i = 0; i < 9; i++)
#pragma unroll
                for (int j = 0; j < 9; j++)
                    acc[i] += sm.Rs[n * 81 + i * 9 + j] * w9[j];
        }

#pragma unroll
        for (int i = 0; i < 9; i++) {
            size_t idx = (((size_t)b * 9 + i) * COUT + o) * CIN + c;
            g_w16[idx] = __float2half(acc[i]);
        }
        return;
    }

    if (blockIdx.x >= 64) {
        // ---------------- margin zeroing (rows never written by xprep) -----
        int idx = blockIdx.x - 64;            // 0..191
        int wid = threadIdx.x >> 5, lane = threadIdx.x & 31;
        int warpGlobal = idx * 8 + wid;       // 0..1535
        for (int pr = warpGlobal; pr < PROWS; pr += 192 * 8) {
            int p = pr - POFF;
            bool interior = false;
            if (p >= 0 && p < 66 * 66) {
                int hp = p / 66, wp = p - hp * 66;
                interior = (hp >= 1 && hp <= 64 && wp >= 1 && wp <= 64);
            }
            if (!interior) {
                uint4* dst = (uint4*)(g_x16 + ((size_t)b * PROWS + pr) * CIN);
                dst[lane] = make_uint4(0, 0, 0, 0);   // 32 lanes x 16B = 512B row
            }
        }
        return;
    }

    // ---------------- xprep (exact R13 logic) ----------------
    int h = blockIdx.x;
    for (int ci0 = 0; ci0 < CIN; ci0 += 64) {
        __syncthreads();
        for (int i = threadIdx.x; i < 64 * 64; i += 256) {
            int cl = i >> 6, w = i & 63;
            sm.t[cl][w] = x[(((size_t)b * CIN + ci0 + cl) * H_ + h) * W_ + w];
        }
        __syncthreads();
        for (int i = threadIdx.x; i < 64 * 64; i += 256) {
            int w = i >> 6, cl = i & 63;
            size_t row = (size_t)b * PROWS + ((h + 1) * 66 + (w + 1) + POFF);
            g_x16[row * CIN + ci0 + cl] = __float2half(sm.t[cl][w]);
        }
    }
}

// ---------------------------------------------------------------------------
// Kernel C: implicit-GEMM conv via mma.sync (fp16 in, fp32 accum).
// EXACT R13 version: CTA 128 pixels x 128 cout, 8 warps (2M x 4N),
// warp tile 64x32, 2 CTAs/SM, 36 stages, 3-stage ring, one barrier/stage.
// ---------------------------------------------------------------------------
#define LDT     144u                 // smem row stride bytes (9 x 16B)
#define A_TILE  (128u * LDT)         // 18432 B
#define B_TILE  (128u * LDT)         // 18432 B
#define OFF_A   0u
#define OFF_B   A_TILE
#define STG_B   (A_TILE + B_TILE)    // 36864 B per stage
#define SMEM_BYTES (3u * STG_B)      // 110592 B

__device__ __forceinline__ void stage_tiles(uint32_t sdst,
                                            const char* X, const char* W,
                                            int c0, int st, int tid) {
    const int tap = st >> 2, kc = st & 3;
    const int dlt = (tap / 3 - 1) * 66 + (tap % 3) - 1;
    const char* sA = X + ((size_t)(c0 + dlt + POFF) * CIN + kc * 64) * 2;
    const char* sB = W + ((size_t)tap * COUT * CIN + kc * 64) * 2;   // W pre-offset by co0
#pragma unroll
    for (int j = 0; j < 4; j++) {
        int idx = j * 256 + tid;              // 0..1023
        int row = idx >> 3, seg = idx & 7;
        CP16(sdst + OFF_A + row * LDT + seg * 16,
             sA + (size_t)row * (CIN * 2) + seg * 16);
    }
#pragma unroll
    for (int j = 0; j < 4; j++) {
        int idx = j * 256 + tid;              // 0..1023
        int row = idx >> 3, seg = idx & 7;
        CP16(sdst + OFF_B + row * LDT + seg * 16,
             sB + (size_t)row * (CIN * 2) + seg * 16);
    }
}

__global__ void __launch_bounds__(256, 2)
conv_mma_kernel(float* __restrict__ out) {
    extern __shared__ char smem[];
    const uint32_t sb = smem_u32(smem);

    const int tid = threadIdx.x;
    const int wid = tid >> 5, lane = tid & 31;
    const int wm = wid >> 2;         // 0..1 : M half (64 rows)
    const int wn = wid & 3;          // 0..3 : N quarter (32 cols)
    const int tile = blockIdx.x, cob = blockIdx.y, b = blockIdx.z;
    const int c0 = tile * NTILE;
    const int co0 = cob * 128;

    const char* X = (const char*)(g_x16 + (size_t)b * PROWS * CIN);
    const char* W = (const char*)(g_w16 + ((size_t)b * 9 * COUT + co0) * CIN);

    float acc[4][4][4];
#pragma unroll
    for (int mt = 0; mt < 4; mt++)
#pragma unroll
        for (int nt = 0; nt < 4; nt++)
#pragma unroll
            for (int k = 0; k < 4; k++) acc[mt][nt][k] = 0.f;

    const uint32_t aRow = (uint32_t)(wm * 64 + (lane & 15)) * LDT + (lane >> 4) * 16;
    const uint32_t bRow = (uint32_t)(wn * 32 + ((lane >> 4) * 8 + (lane & 7))) * LDT
                          + ((lane >> 3) & 1) * 16;

    stage_tiles(sb + 0u * STG_B, X, W, c0, 0, tid);
    CP_COMMIT();
    stage_tiles(sb + 1u * STG_B, X, W, c0, 1, tid);
    CP_COMMIT();

    int bufSel = 0;                   // st % 3 without modulo
    for (int st = 0; st < 36; st++) {
        if (st < 35) CP_WAIT1(); else CP_WAIT0();
        __syncthreads();              // stage st visible; ring slot st+2 free

        // prefetch st+2 BEFORE compute so cp.async latency hides under mma
        if (st + 2 < 36) {
            int slot = bufSel + 2; if (slot >= 3) slot -= 3;
            stage_tiles(sb + (uint32_t)slot * STG_B, X, W, c0, st + 2, tid);
            CP_COMMIT();
        }

        const uint32_t buf = sb + (uint32_t)bufSel * STG_B;
#pragma unroll
        for (int ks = 0; ks < 4; ks++) {
            const uint32_t kb = ks * 32;
            uint32_t a[4][4];
#pragma unroll
            for (int mt = 0; mt < 4; mt++)
                ldm4(a[mt][0], a[mt][1], a[mt][2], a[mt][3],
                     buf + OFF_A + aRow + mt * (16 * LDT) + kb);
#pragma unroll
            for (int pr = 0; pr < 2; pr++) {     // nt pairs
                uint32_t bb[2][2];
                ldm4(bb[0][0], bb[0][1], bb[1][0], bb[1][1],
                     buf + OFF_B + bRow + pr * (16 * LDT) + kb);
#pragma unroll
                for (int mt = 0; mt < 4; mt++) {
                    mma16816(acc[mt][pr * 2],     a[mt], bb[0]);
                    mma16816(acc[mt][pr * 2 + 1], a[mt], bb[1]);
                }
            }
        }

        if (++bufSel == 3) bufSel = 0;
    }

    // ---- epilogue: fragment -> gmem ----
    const int grp = lane >> 2;
#pragma unroll
    for (int mt = 0; mt < 4; mt++) {
#pragma unroll
        for (int half = 0; half < 2; half++) {
            int p = c0 + wm * 64 + mt * 16 + grp + half * 8;
            int hp = p / 66, wp = p - hp * 66;
            if (hp < 1 || hp > 64 || wp < 1 || wp > 64) continue;
            size_t base = (((size_t)b * COUT + co0 + wn * 32) * H_ + (hp - 1)) * W_
                          + (wp - 1);
#pragma unroll
            for (int nt = 0; nt < 4; nt++) {
                int cofs = nt * 8 + (lane & 3) * 2;
                out[base + (size_t)cofs * (H_ * W_)]       = acc[mt][nt][half * 2];
                out[base + (size_t)(cofs + 1) * (H_ * W_)] = acc[mt][nt][half * 2 + 1];
            }
        }
    }
}

// ---------------------------------------------------------------------------
extern "C" void kernel_launch(void* const* d_in, const int* in_sizes, int n_in,
                              void* d_out, int out_size) {
    const float* x       = (const float*)d_in[0];
    const float* thetas  = (const float*)d_in[1];
    const float* scales  = (const float*)d_in[2];
    const float* lambdas = (const float*)d_in[3];
    const float* weight  = (const float*)d_in[4];
    float* out = (float*)d_out;

    cudaFuncSetAttribute(conv_mma_kernel,
                         cudaFuncAttributeMaxDynamicSharedMemorySize, SMEM_BYTES);

    prep_kernel<<<dim3(256, B_, 2), 256>>>(x, weight, thetas, scales, lambdas);
    conv_mma_kernel<<<dim3(NTILES, 2, B_), 256, SMEM_BYTES>>>(out);
}